// round 2
// baseline (speedup 1.0000x reference)
#include <cuda_runtime.h>
#include <math.h>

#define NB 8192
#define BB 64
#define DD 5
#define NE (NB*DD)      // 40960 neighbor edges
#define NT (NB*BB)      // 524288 (node, batch) rows
#define HC 16

// ---------------- device scratch (no runtime allocation allowed) ------------
__device__ float g_xl[(size_t)NT * HC];   // 33.5 MB, layout (n,b,hc)
__device__ float g_xr[(size_t)NT * HC];   // 33.5 MB
__device__ float g_h [(size_t)NT * HC];   // 33.5 MB
__device__ float g_agg[BB * 64];
__device__ int   g_cnt[NB];
__device__ int   g_off[NB + 1];
__device__ int   g_cur[NB];
__device__ int   g_csr[NE];

// ---------------- reverse-CSR construction --------------------------------
__global__ void zero_cnt_kernel() {
    int i = blockIdx.x * blockDim.x + threadIdx.x;
    if (i < NB) g_cnt[i] = 0;
}

__global__ void count_kernel(const int* __restrict__ neighbors) {
    int e = blockIdx.x * blockDim.x + threadIdx.x;
    if (e < NE) atomicAdd(&g_cnt[neighbors[e]], 1);
}

// single block, 1024 threads, 8 counts each -> exclusive prefix into g_off,
// and seeds g_cur with the same offsets (fill cursors).
__global__ void scan_kernel() {
    __shared__ int wsum[32];
    int t = threadIdx.x;
    int v[8];
    int s = 0;
#pragma unroll
    for (int i = 0; i < 8; i++) { v[i] = g_cnt[t * 8 + i]; s += v[i]; }
    unsigned lane = t & 31, wid = t >> 5;
    int x = s;
#pragma unroll
    for (int o = 1; o < 32; o <<= 1) {
        int y = __shfl_up_sync(0xffffffffu, x, o);
        if (lane >= (unsigned)o) x += y;
    }
    if (lane == 31) wsum[wid] = x;
    __syncthreads();
    if (wid == 0) {
        int w = wsum[lane];
#pragma unroll
        for (int o = 1; o < 32; o <<= 1) {
            int y = __shfl_up_sync(0xffffffffu, w, o);
            if (lane >= (unsigned)o) w += y;
        }
        wsum[lane] = w;
    }
    __syncthreads();
    int excl = x - s + (wid ? wsum[wid - 1] : 0);
    int run = excl;
#pragma unroll
    for (int i = 0; i < 8; i++) {
        g_off[t * 8 + i] = run;
        g_cur[t * 8 + i] = run;
        run += v[i];
    }
    if (t == 1023) g_off[NB] = run;
}

__global__ void fill_kernel(const int* __restrict__ neighbors) {
    int e = blockIdx.x * blockDim.x + threadIdx.x;
    if (e < NE) {
        int dst = neighbors[e];
        int pos = atomicAdd(&g_cur[dst], 1);
        g_csr[pos] = e / DD;   // source node m of edge m -> neighbors[m][d]
    }
}

// ---------------- per-layer projection: xl,xr = h @ Wl, h @ Wr -------------
// FIRST: read input x with (b,n,f) layout; else read g_h with (n,b,f) layout.
template <bool FIRST>
__global__ void proj_kernel(const float* __restrict__ xin,
                            const float* __restrict__ Wl,
                            const float* __restrict__ Wr) {
    __shared__ float sW[512];
    int t = threadIdx.x;
    sW[t]       = Wl[t];
    sW[256 + t] = Wr[t];
    __syncthreads();

    int idx = blockIdx.x * 256 + t;      // n*64 + b
    int n = idx >> 6, b = idx & 63;
    const float* src = FIRST ? (xin + ((size_t)b * NB + n) * HC)
                             : (g_h + (size_t)idx * HC);
    float in[16];
    const float4* p4 = (const float4*)src;
#pragma unroll
    for (int i = 0; i < 4; i++) {
        float4 v = p4[i];
        in[4 * i] = v.x; in[4 * i + 1] = v.y; in[4 * i + 2] = v.z; in[4 * i + 3] = v.w;
    }
    float ol[16], orr[16];
#pragma unroll
    for (int o = 0; o < 16; o++) { ol[o] = 0.f; orr[o] = 0.f; }
#pragma unroll
    for (int f = 0; f < 16; f++) {
        float a = in[f];
#pragma unroll
        for (int o = 0; o < 16; o++) {
            ol[o]  = fmaf(a, sW[f * 16 + o], ol[o]);
            orr[o] = fmaf(a, sW[256 + f * 16 + o], orr[o]);
        }
    }
    float4* pl = (float4*)(g_xl + (size_t)idx * HC);
    float4* pr = (float4*)(g_xr + (size_t)idx * HC);
#pragma unroll
    for (int i = 0; i < 4; i++) {
        pl[i] = make_float4(ol[4 * i], ol[4 * i + 1], ol[4 * i + 2], ol[4 * i + 3]);
        pr[i] = make_float4(orr[4 * i], orr[4 * i + 1], orr[4 * i + 2], orr[4 * i + 3]);
    }
}

// ---------------- GATv2 aggregate (online softmax over incoming edges) ----
__global__ void gat_agg_kernel(const float* __restrict__ attw,
                               const float* __restrict__ bias) {
    int idx = blockIdx.x * 256 + threadIdx.x;
    int n = idx >> 6, b = idx & 63;

    float a[16];
#pragma unroll
    for (int j = 0; j < 16; j++) a[j] = __ldg(&attw[j]);

    float xrv[16];
    {
        const float4* pr = (const float4*)(g_xr + (size_t)idx * HC);
#pragma unroll
        for (int i = 0; i < 4; i++) {
            float4 v = pr[i];
            xrv[4 * i] = v.x; xrv[4 * i + 1] = v.y; xrv[4 * i + 2] = v.z; xrv[4 * i + 3] = v.w;
        }
    }
    float v[16];
    {
        const float4* pl = (const float4*)(g_xl + (size_t)idx * HC);  // self edge: src == n
#pragma unroll
        for (int i = 0; i < 4; i++) {
            float4 q = pl[i];
            v[4 * i] = q.x; v[4 * i + 1] = q.y; v[4 * i + 2] = q.z; v[4 * i + 3] = q.w;
        }
    }
    float m[4], s[4], acc[16];
    // initialize online-softmax state from the self edge
#pragma unroll
    for (int h = 0; h < 4; h++) {
        float l = 0.f;
#pragma unroll
        for (int c = 0; c < 4; c++) {
            float tsum = v[h * 4 + c] + xrv[h * 4 + c];
            tsum = tsum > 0.f ? tsum : 0.2f * tsum;      // leaky_relu(0.2)
            l = fmaf(tsum, a[h * 4 + c], l);
        }
        m[h] = l; s[h] = 1.f;
    }
#pragma unroll
    for (int j = 0; j < 16; j++) acc[j] = v[j];

    int beg = g_off[n], end = g_off[n + 1];
    for (int e = beg; e < end; e++) {
        int src = g_csr[e];                               // warp-uniform
        const float4* pl = (const float4*)(g_xl + ((size_t)src * BB + b) * HC);
#pragma unroll
        for (int i = 0; i < 4; i++) {
            float4 q = pl[i];
            v[4 * i] = q.x; v[4 * i + 1] = q.y; v[4 * i + 2] = q.z; v[4 * i + 3] = q.w;
        }
#pragma unroll
        for (int h = 0; h < 4; h++) {
            float l = 0.f;
#pragma unroll
            for (int c = 0; c < 4; c++) {
                float tsum = v[h * 4 + c] + xrv[h * 4 + c];
                tsum = tsum > 0.f ? tsum : 0.2f * tsum;
                l = fmaf(tsum, a[h * 4 + c], l);
            }
            float nm = fmaxf(m[h], l);
            float sc = __expf(m[h] - nm);
            float w  = __expf(l - nm);
            s[h] = fmaf(s[h], sc, w);
            m[h] = nm;
#pragma unroll
            for (int c = 0; c < 4; c++)
                acc[h * 4 + c] = fmaf(acc[h * 4 + c], sc, w * v[h * 4 + c]);
        }
    }

    float outv[16];
#pragma unroll
    for (int h = 0; h < 4; h++) {
        float inv = 1.f / (s[h] + 1e-16f);
#pragma unroll
        for (int c = 0; c < 4; c++)
            outv[h * 4 + c] = acc[h * 4 + c] * inv + __ldg(&bias[h * 4 + c]);
    }
    float4* po = (float4*)(g_h + (size_t)idx * HC);
#pragma unroll
    for (int i = 0; i < 4; i++)
        po[i] = make_float4(outv[4 * i], outv[4 * i + 1], outv[4 * i + 2], outv[4 * i + 3]);
}

// ---------------- mean-pool over nodes + 2-layer tanh MLP ------------------
__global__ void pool_mlp_kernel(const float* __restrict__ Wg1, const float* __restrict__ bg1,
                                const float* __restrict__ Wg2, const float* __restrict__ bg2) {
    int b = blockIdx.x;
    int t = threadIdx.x;           // 512 threads
    int f = t & 15;
    int g = t >> 4;                // 32 row-groups
    float sum = 0.f;
    for (int n = g; n < NB; n += 32)
        sum += g_h[((size_t)n * BB + b) * HC + f];
    __shared__ float red[512];
    red[t] = sum;
    __syncthreads();
    for (int st = 256; st >= 16; st >>= 1) {
        if (t < st) red[t] += red[t + st];
        __syncthreads();
    }
    __shared__ float pool[16];
    __shared__ float g1[32];
    if (t < 16) pool[t] = red[t] * (1.f / (float)NB);
    __syncthreads();
    if (t < 32) {
        float s = bg1[t];
#pragma unroll
        for (int ff = 0; ff < 16; ff++) s = fmaf(pool[ff], Wg1[ff * 32 + t], s);
        g1[t] = tanhf(s);
    }
    __syncthreads();
    if (t < 64) {
        float s = bg2[t];
#pragma unroll
        for (int k = 0; k < 32; k++) s = fmaf(g1[k], Wg2[k * 64 + t], s);
        g_agg[b * 64 + t] = tanhf(s);
    }
}

// ---------------- edge scorer MLP (B x 3 x D items) ------------------------
__device__ __forceinline__ void acc_feat(float* acc1, const float* __restrict__ We1,
                                         int i, float val) {
#pragma unroll
    for (int o = 0; o < 16; o++)
        acc1[o] = fmaf(val, We1[i * 16 + o], acc1[o]);
}

__global__ void scorer_kernel(const int* __restrict__ agent_nodes,
                              const int* __restrict__ neighbors,
                              const float* __restrict__ We1, const float* __restrict__ be1,
                              const float* __restrict__ We2, const float* __restrict__ be2,
                              const float* __restrict__ We3, const float* __restrict__ be3,
                              float* __restrict__ out) {
    int i = blockIdx.x * blockDim.x + threadIdx.x;
    if (i >= BB * 3 * DD) return;
    int b = i / (3 * DD);
    int r = i % (3 * DD);
    int tk = r / DD;
    int d  = r % DD;
    int an = agent_nodes[b];
    int tg = neighbors[an * DD + d];

    float acc1[16];
#pragma unroll
    for (int o = 0; o < 16; o++) acc1[o] = be1[o];

#pragma unroll
    for (int ff = 0; ff < 16; ff++)                         // source features [0,16)
        acc_feat(acc1, We1, ff, g_h[((size_t)an * BB + b) * HC + ff]);
    acc_feat(acc1, We1, 16, tk == 0 ? 1.f : 0.f);           // token one-hot [16,19)
    acc_feat(acc1, We1, 17, tk == 1 ? 1.f : 0.f);
    acc_feat(acc1, We1, 18, tk == 2 ? 1.f : 0.f);
#pragma unroll
    for (int ff = 0; ff < 16; ff++)                         // target features [19,35)
        acc_feat(acc1, We1, 19 + ff, g_h[((size_t)tg * BB + b) * HC + ff]);
#pragma unroll
    for (int k = 0; k < 64; k++)                            // agg features [35,99)
        acc_feat(acc1, We1, 35 + k, g_agg[b * 64 + k]);

    float e1[16];
#pragma unroll
    for (int o = 0; o < 16; o++) e1[o] = tanhf(acc1[o]);

    float e2[8];
#pragma unroll
    for (int o2 = 0; o2 < 8; o2++) {
        float s = be2[o2];
#pragma unroll
        for (int o = 0; o < 16; o++) s = fmaf(e1[o], We2[o * 8 + o2], s);
        e2[o2] = tanhf(s);
    }
    float s3 = be3[0];
#pragma unroll
    for (int o2 = 0; o2 < 8; o2++) s3 = fmaf(e2[o2], We3[o2], s3);
    out[i] = s3;
}

// ---------------- launch ---------------------------------------------------
extern "C" void kernel_launch(void* const* d_in, const int* in_sizes, int n_in,
                              void* d_out, int out_size) {
    const float* x      = (const float*)d_in[0];
    const int*   agent  = (const int*)  d_in[1];
    const int*   nbr    = (const int*)  d_in[2];
    const float* Wl     = (const float*)d_in[3];
    const float* Wr     = (const float*)d_in[4];
    const float* attw   = (const float*)d_in[5];
    const float* bias   = (const float*)d_in[6];
    const float* Wg1    = (const float*)d_in[7];
    const float* bg1    = (const float*)d_in[8];
    const float* Wg2    = (const float*)d_in[9];
    const float* bg2    = (const float*)d_in[10];
    const float* We1    = (const float*)d_in[11];
    const float* be1    = (const float*)d_in[12];
    const float* We2    = (const float*)d_in[13];
    const float* be2    = (const float*)d_in[14];
    const float* We3    = (const float*)d_in[15];
    const float* be3    = (const float*)d_in[16];
    float* out = (float*)d_out;

    // reverse CSR of incoming edges
    zero_cnt_kernel<<<32, 256>>>();
    count_kernel<<<(NE + 255) / 256, 256>>>(nbr);
    scan_kernel<<<1, 1024>>>();
    fill_kernel<<<(NE + 255) / 256, 256>>>(nbr);

    // 4 GATv2 layers
    for (int l = 0; l < 4; l++) {
        if (l == 0)
            proj_kernel<true><<<NT / 256, 256>>>(x, Wl, Wr);
        else
            proj_kernel<false><<<NT / 256, 256>>>(nullptr, Wl + l * 256, Wr + l * 256);
        gat_agg_kernel<<<NT / 256, 256>>>(attw + l * 16, bias + l * 16);
    }

    // pooling + agg MLP, then edge scorer
    pool_mlp_kernel<<<BB, 512>>>(Wg1, bg1, Wg2, bg2);
    scorer_kernel<<<(BB * 3 * DD + 127) / 128, 128>>>(agent, nbr,
                                                      We1, be1, We2, be2, We3, be3, out);
}

// round 3
// speedup vs baseline: 1.1438x; 1.1438x over previous
#include <cuda_runtime.h>
#include <math.h>

#define NB 8192
#define BB 64
#define DD 5
#define NE (NB*DD)      // 40960 neighbor edges
#define NT (NB*BB)      // 524288 (node, batch) rows
#define HC 16

// ---------------- device scratch (no runtime allocation allowed) ------------
__device__ float g_xl [(size_t)NT * HC];   // 33.5 MB, layout (n,b,hc)  (buffer A)
__device__ float g_xl2[(size_t)NT * HC];   // 33.5 MB                   (buffer B)
__device__ float g_h  [(size_t)NT * HC];   // 33.5 MB
__device__ float g_pool[BB * HC];
__device__ float g_agg[BB * 64];
__device__ int   g_cnt[NB];
__device__ int   g_off[NB + 1];
__device__ int   g_cur[NB];
__device__ int   g_csr[NE];

// ---------------- zero counters + pool accumulators ------------------------
__global__ void zero_kernel() {
    int i = blockIdx.x * blockDim.x + threadIdx.x;
    if (i < NB) g_cnt[i] = 0;
    if (i < BB * HC) g_pool[i] = 0.f;
}

__global__ void count_kernel(const int* __restrict__ neighbors) {
    int e = blockIdx.x * blockDim.x + threadIdx.x;
    if (e < NE) atomicAdd(&g_cnt[neighbors[e]], 1);
}

// single block, 1024 threads, 8 counts each -> exclusive prefix into g_off,
// seeds g_cur with the same offsets (fill cursors).
__global__ void scan_kernel() {
    __shared__ int wsum[32];
    int t = threadIdx.x;
    int v[8];
    int s = 0;
#pragma unroll
    for (int i = 0; i < 8; i++) { v[i] = g_cnt[t * 8 + i]; s += v[i]; }
    unsigned lane = t & 31, wid = t >> 5;
    int x = s;
#pragma unroll
    for (int o = 1; o < 32; o <<= 1) {
        int y = __shfl_up_sync(0xffffffffu, x, o);
        if (lane >= (unsigned)o) x += y;
    }
    if (lane == 31) wsum[wid] = x;
    __syncthreads();
    if (wid == 0) {
        int w = wsum[lane];
#pragma unroll
        for (int o = 1; o < 32; o <<= 1) {
            int y = __shfl_up_sync(0xffffffffu, w, o);
            if (lane >= (unsigned)o) w += y;
        }
        wsum[lane] = w;
    }
    __syncthreads();
    int excl = x - s + (wid ? wsum[wid - 1] : 0);
    int run = excl;
#pragma unroll
    for (int i = 0; i < 8; i++) {
        g_off[t * 8 + i] = run;
        g_cur[t * 8 + i] = run;
        run += v[i];
    }
    if (t == 1023) g_off[NB] = run;
}

__global__ void fill_kernel(const int* __restrict__ neighbors) {
    int e = blockIdx.x * blockDim.x + threadIdx.x;
    if (e < NE) {
        int dst = neighbors[e];
        int pos = atomicAdd(&g_cur[dst], 1);
        g_csr[pos] = e / DD;   // source node m of edge m -> neighbors[m][d]
    }
}

// ---------------- layer-0 xl projection: g_xl = x @ Wl0 --------------------
__global__ __launch_bounds__(256)
void xl0_kernel(const float* __restrict__ xin, const float* __restrict__ Wl) {
    __shared__ float sW[256];
    int t = threadIdx.x;
    sW[t] = Wl[t];
    __syncthreads();

    int idx = blockIdx.x * 256 + t;      // n*64 + b
    int n = idx >> 6, b = idx & 63;
    const float* src = xin + ((size_t)b * NB + n) * HC;   // (b, n, f) layout
    float in[16];
    const float4* p4 = (const float4*)src;
#pragma unroll
    for (int i = 0; i < 4; i++) {
        float4 v = p4[i];
        in[4 * i] = v.x; in[4 * i + 1] = v.y; in[4 * i + 2] = v.z; in[4 * i + 3] = v.w;
    }
    float ol[16];
#pragma unroll
    for (int o = 0; o < 16; o++) ol[o] = 0.f;
#pragma unroll
    for (int f = 0; f < 16; f++) {
        float a = in[f];
#pragma unroll
        for (int o = 0; o < 16; o++) ol[o] = fmaf(a, sW[f * 16 + o], ol[o]);
    }
    float4* pl = (float4*)(g_xl + (size_t)idx * HC);
#pragma unroll
    for (int i = 0; i < 4; i++)
        pl[i] = make_float4(ol[4 * i], ol[4 * i + 1], ol[4 * i + 2], ol[4 * i + 3]);
}

// ---------------- fused GATv2 layer ----------------------------------------
// Computes xrv = h_row @ Wr inline, does the online-softmax aggregate over
// incoming edges reading xl from the IN buffer, writes new h, and (if !LAST)
// writes xl for the NEXT layer into the other buffer.
template <int IN, bool FIRST, bool LAST>
__global__ __launch_bounds__(256)
void gat_fused_kernel(const float* __restrict__ hin,   // only used when FIRST (x, (b,n,f))
                      const float* __restrict__ Wr,
                      const float* __restrict__ attw,
                      const float* __restrict__ bias,
                      const float* __restrict__ Wln) { // next layer's Wl (null if LAST)
    __shared__ float sWr[256], sWln[256], satt[16], sbias[16];
    int t = threadIdx.x;
    sWr[t] = Wr[t];
    if (!LAST) sWln[t] = Wln[t];
    if (t < 16) { satt[t] = attw[t]; sbias[t] = bias[t]; }
    __syncthreads();

    const float* __restrict__ xlin  = (IN == 0) ? g_xl : g_xl2;
    float*       __restrict__ xlout = (IN == 0) ? g_xl2 : g_xl;

    int idx = blockIdx.x * 256 + t;      // n*64 + b
    int n = idx >> 6, b = idx & 63;

    // ---- load h row, compute xrv = h @ Wr -------------------------------
    const float* hrow = FIRST ? (hin + ((size_t)b * NB + n) * HC)
                              : (g_h + (size_t)idx * HC);
    float hv[16];
    {
        const float4* p4 = (const float4*)hrow;
#pragma unroll
        for (int i = 0; i < 4; i++) {
            float4 v = p4[i];
            hv[4 * i] = v.x; hv[4 * i + 1] = v.y; hv[4 * i + 2] = v.z; hv[4 * i + 3] = v.w;
        }
    }
    float xrv[16];
#pragma unroll
    for (int o = 0; o < 16; o++) xrv[o] = 0.f;
#pragma unroll
    for (int f = 0; f < 16; f++) {
        float a = hv[f];
#pragma unroll
        for (int o = 0; o < 16; o++) xrv[o] = fmaf(a, sWr[f * 16 + o], xrv[o]);
    }

    // ---- self edge initializes online softmax ---------------------------
    float vv[16];
    {
        const float4* pl = (const float4*)(xlin + (size_t)idx * HC);
#pragma unroll
        for (int i = 0; i < 4; i++) {
            float4 q = pl[i];
            vv[4 * i] = q.x; vv[4 * i + 1] = q.y; vv[4 * i + 2] = q.z; vv[4 * i + 3] = q.w;
        }
    }
    float m[4], s[4], acc[16];
#pragma unroll
    for (int h = 0; h < 4; h++) {
        float l = 0.f;
#pragma unroll
        for (int c = 0; c < 4; c++) {
            float tsum = vv[h * 4 + c] + xrv[h * 4 + c];
            tsum = tsum > 0.f ? tsum : 0.2f * tsum;      // leaky_relu(0.2)
            l = fmaf(tsum, satt[h * 4 + c], l);
        }
        m[h] = l; s[h] = 1.f;
    }
#pragma unroll
    for (int j = 0; j < 16; j++) acc[j] = vv[j];

    // ---- incoming-edge loop with 1-deep prefetch ------------------------
    int beg = g_off[n], end = g_off[n + 1];
    float4 c0, c1, c2, c3;
    c0 = c1 = c2 = c3 = make_float4(0.f, 0.f, 0.f, 0.f);
    if (beg < end) {
        const float4* p = (const float4*)(xlin + ((size_t)g_csr[beg] * BB + b) * HC);
        c0 = p[0]; c1 = p[1]; c2 = p[2]; c3 = p[3];
    }
    for (int e = beg; e < end; e++) {
        float4 d0, d1, d2, d3;
        d0 = d1 = d2 = d3 = make_float4(0.f, 0.f, 0.f, 0.f);
        if (e + 1 < end) {
            const float4* p = (const float4*)(xlin + ((size_t)g_csr[e + 1] * BB + b) * HC);
            d0 = p[0]; d1 = p[1]; d2 = p[2]; d3 = p[3];
        }
        vv[0]  = c0.x; vv[1]  = c0.y; vv[2]  = c0.z; vv[3]  = c0.w;
        vv[4]  = c1.x; vv[5]  = c1.y; vv[6]  = c1.z; vv[7]  = c1.w;
        vv[8]  = c2.x; vv[9]  = c2.y; vv[10] = c2.z; vv[11] = c2.w;
        vv[12] = c3.x; vv[13] = c3.y; vv[14] = c3.z; vv[15] = c3.w;
#pragma unroll
        for (int h = 0; h < 4; h++) {
            float l = 0.f;
#pragma unroll
            for (int c = 0; c < 4; c++) {
                float tsum = vv[h * 4 + c] + xrv[h * 4 + c];
                tsum = tsum > 0.f ? tsum : 0.2f * tsum;
                l = fmaf(tsum, satt[h * 4 + c], l);
            }
            float nm = fmaxf(m[h], l);
            float sc = __expf(m[h] - nm);
            float w  = __expf(l - nm);
            s[h] = fmaf(s[h], sc, w);
            m[h] = nm;
#pragma unroll
            for (int c = 0; c < 4; c++)
                acc[h * 4 + c] = fmaf(acc[h * 4 + c], sc, w * vv[h * 4 + c]);
        }
        c0 = d0; c1 = d1; c2 = d2; c3 = d3;
    }

    // ---- finalize h row --------------------------------------------------
#pragma unroll
    for (int h = 0; h < 4; h++) {
        float inv = 1.f / (s[h] + 1e-16f);
#pragma unroll
        for (int c = 0; c < 4; c++)
            hv[h * 4 + c] = acc[h * 4 + c] * inv + sbias[h * 4 + c];
    }
    {
        float4* po = (float4*)(g_h + (size_t)idx * HC);
#pragma unroll
        for (int i = 0; i < 4; i++)
            po[i] = make_float4(hv[4 * i], hv[4 * i + 1], hv[4 * i + 2], hv[4 * i + 3]);
    }

    // ---- fused next-layer xl projection ---------------------------------
    if (!LAST) {
        float ol[16];
#pragma unroll
        for (int o = 0; o < 16; o++) ol[o] = 0.f;
#pragma unroll
        for (int f = 0; f < 16; f++) {
            float a = hv[f];
#pragma unroll
            for (int o = 0; o < 16; o++) ol[o] = fmaf(a, sWln[f * 16 + o], ol[o]);
        }
        float4* pl = (float4*)(xlout + (size_t)idx * HC);
#pragma unroll
        for (int i = 0; i < 4; i++)
            pl[i] = make_float4(ol[4 * i], ol[4 * i + 1], ol[4 * i + 2], ol[4 * i + 3]);
    }
}

// ---------------- mean-pool over nodes (phase 1: partial sums) -------------
__global__ __launch_bounds__(256)
void pool1_kernel() {
    int b = blockIdx.x >> 3;       // 64 batches
    int chunk = blockIdx.x & 7;    // 8 node chunks of 1024
    int t = threadIdx.x;
    int f = t & 15, g = t >> 4;    // 16 groups
    float sum = 0.f;
    int n0 = chunk * 1024 + g;
    for (int k = 0; k < 64; k++) {
        int n = n0 + k * 16;
        sum += g_h[((size_t)n * BB + b) * HC + f];
    }
    __shared__ float red[256];
    red[t] = sum;
    __syncthreads();
    for (int st = 128; st >= 16; st >>= 1) {
        if (t < st) red[t] += red[t + st];
        __syncthreads();
    }
    if (t < 16) atomicAdd(&g_pool[b * 16 + t], red[t]);
}

// ---------------- agg MLP (phase 2) ---------------------------------------
__global__ void pool2_kernel(const float* __restrict__ Wg1, const float* __restrict__ bg1,
                             const float* __restrict__ Wg2, const float* __restrict__ bg2) {
    int b = blockIdx.x;
    int t = threadIdx.x;   // 64 threads
    __shared__ float pool[16], g1[32];
    if (t < 16) pool[t] = g_pool[b * 16 + t] * (1.f / (float)NB);
    __syncthreads();
    if (t < 32) {
        float s = bg1[t];
#pragma unroll
        for (int ff = 0; ff < 16; ff++) s = fmaf(pool[ff], Wg1[ff * 32 + t], s);
        g1[t] = tanhf(s);
    }
    __syncthreads();
    float s = bg2[t];
#pragma unroll
    for (int k = 0; k < 32; k++) s = fmaf(g1[k], Wg2[k * 64 + t], s);
    g_agg[b * 64 + t] = tanhf(s);
}

// ---------------- edge scorer MLP (B x 3 x D items) ------------------------
__device__ __forceinline__ void acc_feat(float* acc1, const float* __restrict__ We1,
                                         int i, float val) {
#pragma unroll
    for (int o = 0; o < 16; o++)
        acc1[o] = fmaf(val, We1[i * 16 + o], acc1[o]);
}

__global__ void scorer_kernel(const int* __restrict__ agent_nodes,
                              const int* __restrict__ neighbors,
                              const float* __restrict__ We1, const float* __restrict__ be1,
                              const float* __restrict__ We2, const float* __restrict__ be2,
                              const float* __restrict__ We3, const float* __restrict__ be3,
                              float* __restrict__ out) {
    int i = blockIdx.x * blockDim.x + threadIdx.x;
    if (i >= BB * 3 * DD) return;
    int b = i / (3 * DD);
    int r = i % (3 * DD);
    int tk = r / DD;
    int d  = r % DD;
    int an = agent_nodes[b];
    int tg = neighbors[an * DD + d];

    float acc1[16];
#pragma unroll
    for (int o = 0; o < 16; o++) acc1[o] = be1[o];

#pragma unroll
    for (int ff = 0; ff < 16; ff++)                         // source features [0,16)
        acc_feat(acc1, We1, ff, g_h[((size_t)an * BB + b) * HC + ff]);
    acc_feat(acc1, We1, 16, tk == 0 ? 1.f : 0.f);           // token one-hot [16,19)
    acc_feat(acc1, We1, 17, tk == 1 ? 1.f : 0.f);
    acc_feat(acc1, We1, 18, tk == 2 ? 1.f : 0.f);
#pragma unroll
    for (int ff = 0; ff < 16; ff++)                         // target features [19,35)
        acc_feat(acc1, We1, 19 + ff, g_h[((size_t)tg * BB + b) * HC + ff]);
#pragma unroll
    for (int k = 0; k < 64; k++)                            // agg features [35,99)
        acc_feat(acc1, We1, 35 + k, g_agg[b * 64 + k]);

    float e1[16];
#pragma unroll
    for (int o = 0; o < 16; o++) e1[o] = tanhf(acc1[o]);

    float e2[8];
#pragma unroll
    for (int o2 = 0; o2 < 8; o2++) {
        float s = be2[o2];
#pragma unroll
        for (int o = 0; o < 16; o++) s = fmaf(e1[o], We2[o * 8 + o2], s);
        e2[o2] = tanhf(s);
    }
    float s3 = be3[0];
#pragma unroll
    for (int o2 = 0; o2 < 8; o2++) s3 = fmaf(e2[o2], We3[o2], s3);
    out[i] = s3;
}

// ---------------- launch ---------------------------------------------------
extern "C" void kernel_launch(void* const* d_in, const int* in_sizes, int n_in,
                              void* d_out, int out_size) {
    const float* x      = (const float*)d_in[0];
    const int*   agent  = (const int*)  d_in[1];
    const int*   nbr    = (const int*)  d_in[2];
    const float* Wl     = (const float*)d_in[3];
    const float* Wr     = (const float*)d_in[4];
    const float* attw   = (const float*)d_in[5];
    const float* bias   = (const float*)d_in[6];
    const float* Wg1    = (const float*)d_in[7];
    const float* bg1    = (const float*)d_in[8];
    const float* Wg2    = (const float*)d_in[9];
    const float* bg2    = (const float*)d_in[10];
    const float* We1    = (const float*)d_in[11];
    const float* be1    = (const float*)d_in[12];
    const float* We2    = (const float*)d_in[13];
    const float* be2    = (const float*)d_in[14];
    const float* We3    = (const float*)d_in[15];
    const float* be3    = (const float*)d_in[16];
    float* out = (float*)d_out;

    // reverse CSR of incoming edges (+ zero pool accumulators)
    zero_kernel<<<32, 256>>>();
    count_kernel<<<(NE + 255) / 256, 256>>>(nbr);
    scan_kernel<<<1, 1024>>>();
    fill_kernel<<<(NE + 255) / 256, 256>>>(nbr);

    // layer-0 xl projection into buffer A
    xl0_kernel<<<NT / 256, 256>>>(x, Wl);

    // 4 fused GATv2 layers (xl buffers ping-pong A->B->A->B)
    gat_fused_kernel<0, true,  false><<<NT / 256, 256>>>(x, Wr,       attw,      bias,      Wl + 256);
    gat_fused_kernel<1, false, false><<<NT / 256, 256>>>(x, Wr + 256, attw + 16, bias + 16, Wl + 512);
    gat_fused_kernel<0, false, false><<<NT / 256, 256>>>(x, Wr + 512, attw + 32, bias + 32, Wl + 768);
    gat_fused_kernel<1, false, true ><<<NT / 256, 256>>>(x, Wr + 768, attw + 48, bias + 48, nullptr);

    // pooling + agg MLP, then edge scorer
    pool1_kernel<<<BB * 8, 256>>>();
    pool2_kernel<<<BB, 64>>>(Wg1, bg1, Wg2, bg2);
    scorer_kernel<<<(BB * 3 * DD + 127) / 128, 128>>>(agent, nbr,
                                                      We1, be1, We2, be2, We3, be3, out);
}